// round 1
// baseline (speedup 1.0000x reference)
#include <cuda_runtime.h>
#include <cuda_bf16.h>
#include <math.h>

// Problem constants
#define T_TOK   2048      // B*S = 2*1024
#define H_DIM   1024
#define E_NUM   16
#define I_DIM   1024
#define NPAIR   (T_TOK*2) // 4096 (token,expert) pairs, top-2

// Scratch (device globals; no cudaMalloc allowed)
__device__ float g_act [NPAIR * I_DIM];   // 16 MB: w * silu(g) * u, expert-sorted slots
__device__ float g_part[NPAIR * H_DIM];   // 16 MB: down-projection per pair slot
__device__ int   g_expert_of[NPAIR];      // per (t,k): expert id
__device__ float g_weight_of[NPAIR];      // per (t,k): normalized weight
__device__ int   g_base [E_NUM];
__device__ int   g_count[E_NUM];
__device__ int   g_pair_token[NPAIR];     // slot -> token
__device__ float g_pair_w   [NPAIR];      // slot -> weight
__device__ int   g_slot_of  [NPAIR];      // (t,k) -> slot

// ---------------------------------------------------------------------------
// 1) Router: logits -> sigmoid -> top2 -> normalize
//    one block per token, 16 warps = 16 experts
// ---------------------------------------------------------------------------
__global__ void router_kernel(const float* __restrict__ x,
                              const float* __restrict__ rw) {
    int t = blockIdx.x;
    int warp = threadIdx.x >> 5, lane = threadIdx.x & 31;
    __shared__ float logits[E_NUM];
    const float* xr = x + (size_t)t * H_DIM;
    const float* wr = rw + (size_t)warp * H_DIM;
    float s = 0.f;
    #pragma unroll 4
    for (int h = lane; h < H_DIM; h += 32) s += xr[h] * wr[h];
    #pragma unroll
    for (int o = 16; o; o >>= 1) s += __shfl_xor_sync(0xffffffffu, s, o);
    if (lane == 0) logits[warp] = s;
    __syncthreads();
    if (threadIdx.x == 0) {
        float sc[E_NUM];
        #pragma unroll
        for (int e = 0; e < E_NUM; e++) sc[e] = 1.f / (1.f + expf(-logits[e]));
        int i0 = 0;
        #pragma unroll
        for (int e = 1; e < E_NUM; e++) if (sc[e] > sc[i0]) i0 = e;
        int i1 = -1;
        #pragma unroll
        for (int e = 0; e < E_NUM; e++) {
            if (e == i0) continue;
            if (i1 < 0 || sc[e] > sc[i1]) i1 = e;
        }
        float w0 = sc[i0], w1 = sc[i1];
        float inv = 1.f / (w0 + w1 + 1e-20f);
        g_expert_of[2*t]   = i0;  g_weight_of[2*t]   = w0 * inv;
        g_expert_of[2*t+1] = i1;  g_weight_of[2*t+1] = w1 * inv;
    }
}

// ---------------------------------------------------------------------------
// 2) Build expert-sorted pair lists (single block, deterministic)
// ---------------------------------------------------------------------------
__global__ void build_kernel() {
    __shared__ unsigned char eid[NPAIR];
    __shared__ int cnt[E_NUM], bs[E_NUM];
    int tid = threadIdx.x;
    for (int p = tid; p < NPAIR; p += blockDim.x)
        eid[p] = (unsigned char)g_expert_of[p];
    __syncthreads();
    if (tid < E_NUM) {
        int c = 0;
        for (int p = 0; p < NPAIR; p++) c += (eid[p] == tid);
        cnt[tid] = c;
    }
    __syncthreads();
    if (tid == 0) {
        int acc = 0;
        for (int e = 0; e < E_NUM; e++) { bs[e] = acc; acc += cnt[e]; }
    }
    __syncthreads();
    int w = tid >> 5, lane = tid & 31;
    if (w < E_NUM) {
        int e = w, pos = bs[e];
        for (int p0 = 0; p0 < NPAIR; p0 += 32) {
            int p = p0 + lane;
            bool m = (eid[p] == e);
            unsigned mask = __ballot_sync(0xffffffffu, m);
            if (m) {
                int s = pos + __popc(mask & ((1u << lane) - 1u));
                g_pair_token[s] = p >> 1;
                g_pair_w[s]     = g_weight_of[p];
                g_slot_of[p]    = s;
            }
            pos += __popc(mask);
        }
    }
    if (tid < E_NUM) { g_base[tid] = bs[tid]; g_count[tid] = cnt[tid]; }
}

// ---------------------------------------------------------------------------
// 3) Grouped GEMM: gate + up fused, SiLU, weight fold -> g_act
//    Tile 64x64, BK=16, 256 threads, 4x4 microtile, two accumulator sets.
// ---------------------------------------------------------------------------
#define BM 64
#define BN 64
#define BK 16

__global__ __launch_bounds__(256)
void gateup_kernel(const float* __restrict__ x,
                   const float* __restrict__ gate_w,
                   const float* __restrict__ up_w) {
    int e  = blockIdx.z;
    int m0 = blockIdx.y * BM;
    int n0 = blockIdx.x * BN;
    int cnt = g_count[e];
    if (m0 >= cnt) return;
    int bse = g_base[e];

    __shared__ float As[BK][BM];
    __shared__ float Bg[BK][BN];
    __shared__ float Bu[BK][BN];
    __shared__ int   tok[BM];
    __shared__ float wrow[BM];

    int tid = threadIdx.x;
    if (tid < BM) {
        int m = m0 + tid;
        bool valid = m < cnt;
        tok[tid]  = valid ? g_pair_token[bse + m] : 0;
        wrow[tid] = valid ? g_pair_w[bse + m] : 0.f;
    }
    __syncthreads();

    const float* Gb = gate_w + ((size_t)e << 20) + (size_t)n0 * H_DIM;
    const float* Ub = up_w   + ((size_t)e << 20) + (size_t)n0 * H_DIM;

    float cg[4][4] = {}, cu[4][4] = {};
    int tx = tid & 15, ty = tid >> 4;

    // loader mapping: lane-major rows => conflict-free smem writes
    int lr = tid & 63;            // row in tile (m or n)
    int kq = (tid >> 6) << 2;     // k sub-offset 0,4,8,12
    int mlim = cnt - m0;          // valid A rows in this tile

    for (int k0 = 0; k0 < H_DIM; k0 += BK) {
        float4 a = (lr < mlim)
            ? *(const float4*)(x + (size_t)tok[lr] * H_DIM + k0 + kq)
            : make_float4(0.f, 0.f, 0.f, 0.f);
        float4 g = *(const float4*)(Gb + (size_t)lr * H_DIM + k0 + kq);
        float4 u = *(const float4*)(Ub + (size_t)lr * H_DIM + k0 + kq);
        As[kq+0][lr] = a.x; As[kq+1][lr] = a.y; As[kq+2][lr] = a.z; As[kq+3][lr] = a.w;
        Bg[kq+0][lr] = g.x; Bg[kq+1][lr] = g.y; Bg[kq+2][lr] = g.z; Bg[kq+3][lr] = g.w;
        Bu[kq+0][lr] = u.x; Bu[kq+1][lr] = u.y; Bu[kq+2][lr] = u.z; Bu[kq+3][lr] = u.w;
        __syncthreads();
        #pragma unroll
        for (int k = 0; k < BK; k++) {
            float4 av = *(const float4*)&As[k][ty * 4];
            float4 gv = *(const float4*)&Bg[k][tx * 4];
            float4 uv = *(const float4*)&Bu[k][tx * 4];
            float am[4] = {av.x, av.y, av.z, av.w};
            float gm[4] = {gv.x, gv.y, gv.z, gv.w};
            float um[4] = {uv.x, uv.y, uv.z, uv.w};
            #pragma unroll
            for (int i = 0; i < 4; i++)
                #pragma unroll
                for (int j = 0; j < 4; j++) {
                    cg[i][j] += am[i] * gm[j];
                    cu[i][j] += am[i] * um[j];
                }
        }
        __syncthreads();
    }

    #pragma unroll
    for (int i = 0; i < 4; i++) {
        int mr = ty * 4 + i;
        int m  = m0 + mr;
        if (m >= cnt) break;
        float w = wrow[mr];
        float* arow = g_act + (size_t)(bse + m) * I_DIM + n0 + tx * 4;
        #pragma unroll
        for (int j = 0; j < 4; j++) {
            float gval = cg[i][j];
            float sil  = gval / (1.f + expf(-gval));
            arow[j] = w * sil * cu[i][j];
        }
    }
}

// ---------------------------------------------------------------------------
// 4) Grouped GEMM: down projection -> g_part
// ---------------------------------------------------------------------------
__global__ __launch_bounds__(256)
void down_kernel(const float* __restrict__ down_w) {
    int e  = blockIdx.z;
    int m0 = blockIdx.y * BM;
    int n0 = blockIdx.x * BN;
    int cnt = g_count[e];
    if (m0 >= cnt) return;
    int bse = g_base[e];

    __shared__ float As[BK][BM];
    __shared__ float Bd[BK][BN];

    int tid = threadIdx.x;
    const float* Db = down_w + ((size_t)e << 20) + (size_t)n0 * I_DIM;
    const float* Ab = g_act + (size_t)bse * I_DIM;

    float cc[4][4] = {};
    int tx = tid & 15, ty = tid >> 4;
    int lr = tid & 63;
    int kq = (tid >> 6) << 2;
    int mlim = cnt - m0;

    for (int k0 = 0; k0 < I_DIM; k0 += BK) {
        float4 a = (lr < mlim)
            ? *(const float4*)(Ab + (size_t)(m0 + lr) * I_DIM + k0 + kq)
            : make_float4(0.f, 0.f, 0.f, 0.f);
        float4 d = *(const float4*)(Db + (size_t)lr * I_DIM + k0 + kq);
        As[kq+0][lr] = a.x; As[kq+1][lr] = a.y; As[kq+2][lr] = a.z; As[kq+3][lr] = a.w;
        Bd[kq+0][lr] = d.x; Bd[kq+1][lr] = d.y; Bd[kq+2][lr] = d.z; Bd[kq+3][lr] = d.w;
        __syncthreads();
        #pragma unroll
        for (int k = 0; k < BK; k++) {
            float4 av = *(const float4*)&As[k][ty * 4];
            float4 dv = *(const float4*)&Bd[k][tx * 4];
            float am[4] = {av.x, av.y, av.z, av.w};
            float dm[4] = {dv.x, dv.y, dv.z, dv.w};
            #pragma unroll
            for (int i = 0; i < 4; i++)
                #pragma unroll
                for (int j = 0; j < 4; j++)
                    cc[i][j] += am[i] * dm[j];
        }
        __syncthreads();
    }

    #pragma unroll
    for (int i = 0; i < 4; i++) {
        int m = m0 + ty * 4 + i;
        if (m >= cnt) break;
        float* prow = g_part + (size_t)(bse + m) * H_DIM + n0 + tx * 4;
        #pragma unroll
        for (int j = 0; j < 4; j++) prow[j] = cc[i][j];
    }
}

// ---------------------------------------------------------------------------
// 5) Combine: out[t] = part[slot(t,0)] + part[slot(t,1)]  (fixed order)
// ---------------------------------------------------------------------------
__global__ void combine_kernel(float* __restrict__ out) {
    int t = blockIdx.x;
    int s0 = g_slot_of[2*t], s1 = g_slot_of[2*t + 1];
    const float4* p0 = (const float4*)(g_part + (size_t)s0 * H_DIM);
    const float4* p1 = (const float4*)(g_part + (size_t)s1 * H_DIM);
    float4* o = (float4*)(out + (size_t)t * H_DIM);
    for (int i = threadIdx.x; i < H_DIM / 4; i += blockDim.x) {
        float4 a = p0[i], b = p1[i];
        o[i] = make_float4(a.x + b.x, a.y + b.y, a.z + b.z, a.w + b.w);
    }
}

// ---------------------------------------------------------------------------
extern "C" void kernel_launch(void* const* d_in, const int* in_sizes, int n_in,
                              void* d_out, int out_size) {
    const float* hidden   = (const float*)d_in[0];
    const float* router_w = (const float*)d_in[1];
    const float* gate_w   = (const float*)d_in[2];
    const float* up_w     = (const float*)d_in[3];
    const float* down_w   = (const float*)d_in[4];
    float* out = (float*)d_out;

    router_kernel<<<T_TOK, 512>>>(hidden, router_w);
    build_kernel<<<1, 512>>>();

    dim3 gridC(I_DIM / BN, T_TOK / BM, E_NUM);   // (16, 32, 16) w/ early exit
    gateup_kernel<<<gridC, 256>>>(hidden, gate_w, up_w);

    dim3 gridD(H_DIM / BN, T_TOK / BM, E_NUM);
    down_kernel<<<gridD, 256>>>(down_w);

    combine_kernel<<<T_TOK, 256>>>(out);
}

// round 3
// speedup vs baseline: 3.4418x; 3.4418x over previous
#include <cuda_runtime.h>
#include <cuda_fp16.h>
#include <math.h>
#include <cstdint>

// Problem constants
#define T_TOK   2048
#define H_DIM   1024
#define E_NUM   16
#define I_DIM   1024
#define NPAIR   (T_TOK*2)

// Scratch (device globals)
__device__ __half g_act [NPAIR * I_DIM];   // 8 MB fp16 activations (expert-sorted)
__device__ float  g_part[NPAIR * H_DIM];   // 16 MB down-proj partials
__device__ int    g_expert_of[NPAIR];
__device__ float  g_weight_of[NPAIR];
__device__ int    g_base [E_NUM];
__device__ int    g_count[E_NUM];
__device__ int    g_pair_token[NPAIR];
__device__ float  g_pair_w   [NPAIR];
__device__ int    g_slot_of  [NPAIR];

// ---------------------------------------------------------------------------
// helpers
// ---------------------------------------------------------------------------
__device__ __forceinline__ uint32_t smem_u32(const void* p) {
    uint32_t a;
    asm("{ .reg .u64 t; cvta.to.shared.u64 t, %1; cvt.u32.u64 %0, t; }" : "=r"(a) : "l"(p));
    return a;
}
__device__ __forceinline__ void ldsm_x4(uint32_t* r, uint32_t addr) {
    asm volatile("ldmatrix.sync.aligned.m8n8.x4.shared.b16 {%0,%1,%2,%3}, [%4];"
                 : "=r"(r[0]), "=r"(r[1]), "=r"(r[2]), "=r"(r[3]) : "r"(addr));
}
__device__ __forceinline__ void ldsm_x2(uint32_t* r, uint32_t addr) {
    asm volatile("ldmatrix.sync.aligned.m8n8.x2.shared.b16 {%0,%1}, [%2];"
                 : "=r"(r[0]), "=r"(r[1]) : "r"(addr));
}
__device__ __forceinline__ void mma16816(float* c, const uint32_t* a, const uint32_t* b) {
    asm volatile("mma.sync.aligned.m16n8k16.row.col.f32.f16.f16.f32 "
                 "{%0,%1,%2,%3}, {%4,%5,%6,%7}, {%8,%9}, {%0,%1,%2,%3};"
                 : "+f"(c[0]), "+f"(c[1]), "+f"(c[2]), "+f"(c[3])
                 : "r"(a[0]), "r"(a[1]), "r"(a[2]), "r"(a[3]), "r"(b[0]), "r"(b[1]));
}
__device__ __forceinline__ uint32_t packh2(float x, float y) {
    __half2 h = __floats2half2_rn(x, y);
    return *(uint32_t*)&h;
}

// smem row pitch in halfs: 32 (K-slab) + 8 pad
#define PITCH 40

// ---------------------------------------------------------------------------
// 1) Router
// ---------------------------------------------------------------------------
__global__ void router_kernel(const float* __restrict__ x,
                              const float* __restrict__ rw) {
    int t = blockIdx.x;
    int warp = threadIdx.x >> 5, lane = threadIdx.x & 31;
    __shared__ float logits[E_NUM];
    const float* xr = x + (size_t)t * H_DIM;
    const float* wr = rw + (size_t)warp * H_DIM;
    float s = 0.f;
    #pragma unroll 4
    for (int h = lane; h < H_DIM; h += 32) s += xr[h] * wr[h];
    #pragma unroll
    for (int o = 16; o; o >>= 1) s += __shfl_xor_sync(0xffffffffu, s, o);
    if (lane == 0) logits[warp] = s;
    __syncthreads();
    if (threadIdx.x == 0) {
        float sc[E_NUM];
        #pragma unroll
        for (int e = 0; e < E_NUM; e++) sc[e] = 1.f / (1.f + expf(-logits[e]));
        int i0 = 0;
        #pragma unroll
        for (int e = 1; e < E_NUM; e++) if (sc[e] > sc[i0]) i0 = e;
        int i1 = -1;
        #pragma unroll
        for (int e = 0; e < E_NUM; e++) {
            if (e == i0) continue;
            if (i1 < 0 || sc[e] > sc[i1]) i1 = e;
        }
        float w0 = sc[i0], w1 = sc[i1];
        float inv = 1.f / (w0 + w1 + 1e-20f);
        g_expert_of[2*t]   = i0;  g_weight_of[2*t]   = w0 * inv;
        g_expert_of[2*t+1] = i1;  g_weight_of[2*t+1] = w1 * inv;
    }
}

// ---------------------------------------------------------------------------
// 2) Build expert-sorted pair lists
// ---------------------------------------------------------------------------
__global__ void build_kernel() {
    __shared__ unsigned char eid[NPAIR];
    __shared__ int cnt[E_NUM], bs[E_NUM];
    int tid = threadIdx.x;
    for (int p = tid; p < NPAIR; p += blockDim.x)
        eid[p] = (unsigned char)g_expert_of[p];
    __syncthreads();
    if (tid < E_NUM) {
        int c = 0;
        for (int p = 0; p < NPAIR; p++) c += (eid[p] == tid);
        cnt[tid] = c;
    }
    __syncthreads();
    if (tid == 0) {
        int acc = 0;
        for (int e = 0; e < E_NUM; e++) { bs[e] = acc; acc += cnt[e]; }
    }
    __syncthreads();
    int w = tid >> 5, lane = tid & 31;
    if (w < E_NUM) {
        int e = w, pos = bs[e];
        for (int p0 = 0; p0 < NPAIR; p0 += 32) {
            int p = p0 + lane;
            bool m = (eid[p] == e);
            unsigned mask = __ballot_sync(0xffffffffu, m);
            if (m) {
                int s = pos + __popc(mask & ((1u << lane) - 1u));
                g_pair_token[s] = p >> 1;
                g_pair_w[s]     = g_weight_of[p];
                g_slot_of[p]    = s;
            }
            pos += __popc(mask);
        }
    }
    if (tid < E_NUM) { g_base[tid] = bs[tid]; g_count[tid] = cnt[tid]; }
}

// ---------------------------------------------------------------------------
// 3) gateup: mma.sync fp16 grouped GEMM, gate+up fused, SiLU + weight fold
//    CTA tile: 128(M) x 64(N per matrix) x 32(K). 256 threads (8 warps 4mx2n).
// ---------------------------------------------------------------------------
__global__ __launch_bounds__(256)
void gateup_mma(const float* __restrict__ x,
                const float* __restrict__ gate_w,
                const float* __restrict__ up_w) {
    int e  = blockIdx.z;
    int m0 = blockIdx.y * 128;
    int n0 = blockIdx.x * 64;
    int cnt = g_count[e];
    if (m0 >= cnt) return;
    int bse = g_base[e];

    __shared__ __half As [128][PITCH];
    __shared__ __half Bgs[64][PITCH];
    __shared__ __half Bus[64][PITCH];
    __shared__ int    tok_s[128];
    __shared__ float  wrow_s[128];

    int tid = threadIdx.x, lane = tid & 31, wid = tid >> 5;
    if (tid < 128) {
        int m = m0 + tid;
        bool v = m < cnt;
        int mc = v ? m : (cnt - 1);
        tok_s[tid]  = g_pair_token[bse + mc];
        wrow_s[tid] = v ? g_pair_w[bse + m] : 0.f;
    }
    __syncthreads();

    const float* Gb = gate_w + ((size_t)e << 20) + (size_t)n0 * H_DIM;
    const float* Ub = up_w   + ((size_t)e << 20) + (size_t)n0 * H_DIM;

    // warp tile: 32(m) x 32(n), mtiles=2, ntiles=4
    int wm = wid & 3, wn = wid >> 2;
    int m_base = wm * 32, n_base = wn * 32;

    uint32_t as_base = smem_u32(&As[0][0]);
    uint32_t bg_base = smem_u32(&Bgs[0][0]);
    uint32_t bu_base = smem_u32(&Bus[0][0]);

    uint32_t addrA[2];
    #pragma unroll
    for (int i = 0; i < 2; i++)
        addrA[i] = as_base + (uint32_t)((m_base + i*16 + (lane & 15)) * (PITCH*2)) + ((lane >> 4) * 16);
    uint32_t addrBg[4], addrBu[4];
    #pragma unroll
    for (int j = 0; j < 4; j++) {
        uint32_t off = (uint32_t)((n_base + j*8 + (lane & 7)) * (PITCH*2)) + (((lane >> 3) & 1) * 16);
        addrBg[j] = bg_base + off;
        addrBu[j] = bu_base + off;
    }

    float cg[2][4][4] = {}, cu[2][4][4] = {};

    float4 ra[4], rg[2], ru[2];
    // prefetch k0 = 0
    #pragma unroll
    for (int j = 0; j < 4; j++) {
        int idx = j*256 + tid, r = idx >> 3, c = idx & 7;
        ra[j] = *(const float4*)(x + (size_t)tok_s[r] * H_DIM + c*4);
    }
    #pragma unroll
    for (int j = 0; j < 2; j++) {
        int idx = j*256 + tid, r = idx >> 3, c = idx & 7;
        rg[j] = *(const float4*)(Gb + (size_t)r * H_DIM + c*4);
        ru[j] = *(const float4*)(Ub + (size_t)r * H_DIM + c*4);
    }

    for (int it = 0; it < H_DIM/32; it++) {
        // STS (convert fp32 -> fp16)
        #pragma unroll
        for (int j = 0; j < 4; j++) {
            int idx = j*256 + tid, r = idx >> 3, c = idx & 7;
            uint2 u; u.x = packh2(ra[j].x, ra[j].y); u.y = packh2(ra[j].z, ra[j].w);
            *(uint2*)&As[r][c*4] = u;
        }
        #pragma unroll
        for (int j = 0; j < 2; j++) {
            int idx = j*256 + tid, r = idx >> 3, c = idx & 7;
            uint2 ug; ug.x = packh2(rg[j].x, rg[j].y); ug.y = packh2(rg[j].z, rg[j].w);
            *(uint2*)&Bgs[r][c*4] = ug;
            uint2 uu; uu.x = packh2(ru[j].x, ru[j].y); uu.y = packh2(ru[j].z, ru[j].w);
            *(uint2*)&Bus[r][c*4] = uu;
        }
        __syncthreads();

        // prefetch next slab
        if (it + 1 < H_DIM/32) {
            int k0 = (it + 1) * 32;
            #pragma unroll
            for (int j = 0; j < 4; j++) {
                int idx = j*256 + tid, r = idx >> 3, c = idx & 7;
                ra[j] = *(const float4*)(x + (size_t)tok_s[r] * H_DIM + k0 + c*4);
            }
            #pragma unroll
            for (int j = 0; j < 2; j++) {
                int idx = j*256 + tid, r = idx >> 3, c = idx & 7;
                rg[j] = *(const float4*)(Gb + (size_t)r * H_DIM + k0 + c*4);
                ru[j] = *(const float4*)(Ub + (size_t)r * H_DIM + k0 + c*4);
            }
        }

        // compute 2 ksteps of 16
        #pragma unroll
        for (int ks = 0; ks < 2; ks++) {
            uint32_t a[2][4];
            #pragma unroll
            for (int i = 0; i < 2; i++) ldsm_x4(a[i], addrA[i] + ks*32);
            uint32_t bg[4][2], bu[4][2];
            #pragma unroll
            for (int j = 0; j < 4; j++) {
                ldsm_x2(bg[j], addrBg[j] + ks*32);
                ldsm_x2(bu[j], addrBu[j] + ks*32);
            }
            #pragma unroll
            for (int i = 0; i < 2; i++)
                #pragma unroll
                for (int j = 0; j < 4; j++) {
                    mma16816(cg[i][j], a[i], bg[j]);
                    mma16816(cu[i][j], a[i], bu[j]);
                }
        }
        __syncthreads();
    }

    // epilogue: act = w * silu(gate) * up  -> fp16
    #pragma unroll
    for (int i = 0; i < 2; i++) {
        #pragma unroll
        for (int h = 0; h < 2; h++) {
            int ml = m_base + i*16 + h*8 + (lane >> 2);
            int m  = m0 + ml;
            if (m >= cnt) continue;
            float w = wrow_s[ml];
            __half* arow = g_act + (size_t)(bse + m) * I_DIM + n0;
            #pragma unroll
            for (int j = 0; j < 4; j++) {
                int nl = n_base + j*8 + 2*(lane & 3);
                float g0 = cg[i][j][h*2+0], g1 = cg[i][j][h*2+1];
                float u0 = cu[i][j][h*2+0], u1 = cu[i][j][h*2+1];
                float a0 = w * (g0 / (1.f + __expf(-g0))) * u0;
                float a1 = w * (g1 / (1.f + __expf(-g1))) * u1;
                *(uint32_t*)&arow[nl] = packh2(a0, a1);
            }
        }
    }
}

// ---------------------------------------------------------------------------
// 4) down: mma.sync fp16 grouped GEMM -> g_part (fp32)
//    CTA tile: 128(M) x 128(N) x 32(K). 256 threads (8 warps 4mx2n).
// ---------------------------------------------------------------------------
__global__ __launch_bounds__(256)
void down_mma(const float* __restrict__ down_w) {
    int e  = blockIdx.z;
    int m0 = blockIdx.y * 128;
    int n0 = blockIdx.x * 128;
    int cnt = g_count[e];
    if (m0 >= cnt) return;
    int bse = g_base[e];

    __shared__ __half As[128][PITCH];
    __shared__ __half Bs[128][PITCH];

    int tid = threadIdx.x, lane = tid & 31, wid = tid >> 5;
    int mlim = cnt - m0;

    const float* Db = down_w + ((size_t)e << 20) + (size_t)n0 * I_DIM;

    // warp tile: 32(m) x 64(n), mtiles=2, ntiles=8
    int wm = wid & 3, wn = wid >> 2;
    int m_base = wm * 32, n_base = wn * 64;

    uint32_t as_base = smem_u32(&As[0][0]);
    uint32_t bs_base = smem_u32(&Bs[0][0]);
    uint32_t addrA[2];
    #pragma unroll
    for (int i = 0; i < 2; i++)
        addrA[i] = as_base + (uint32_t)((m_base + i*16 + (lane & 15)) * (PITCH*2)) + ((lane >> 4) * 16);
    uint32_t addrB[8];
    #pragma unroll
    for (int j = 0; j < 8; j++)
        addrB[j] = bs_base + (uint32_t)((n_base + j*8 + (lane & 7)) * (PITCH*2)) + (((lane >> 3) & 1) * 16);

    float cc[2][8][4] = {};

    uint4  raw[2];   // A: fp16 rows, 8 halfs per uint4
    float4 rb[4];    // B: fp32

    // prefetch k0 = 0
    #pragma unroll
    for (int j = 0; j < 2; j++) {
        int idx = j*256 + tid, r = idx >> 2, c = idx & 3;
        int rc = (r < mlim) ? r : (mlim - 1);
        raw[j] = *(const uint4*)(g_act + (size_t)(bse + m0 + rc) * I_DIM + c*8);
    }
    #pragma unroll
    for (int j = 0; j < 4; j++) {
        int idx = j*256 + tid, r = idx >> 3, c = idx & 7;
        rb[j] = *(const float4*)(Db + (size_t)r * I_DIM + c*4);
    }

    for (int it = 0; it < I_DIM/32; it++) {
        #pragma unroll
        for (int j = 0; j < 2; j++) {
            int idx = j*256 + tid, r = idx >> 2, c = idx & 3;
            *(uint4*)&As[r][c*8] = raw[j];
        }
        #pragma unroll
        for (int j = 0; j < 4; j++) {
            int idx = j*256 + tid, r = idx >> 3, c = idx & 7;
            uint2 u; u.x = packh2(rb[j].x, rb[j].y); u.y = packh2(rb[j].z, rb[j].w);
            *(uint2*)&Bs[r][c*4] = u;
        }
        __syncthreads();

        if (it + 1 < I_DIM/32) {
            int k0 = (it + 1) * 32;
            #pragma unroll
            for (int j = 0; j < 2; j++) {
                int idx = j*256 + tid, r = idx >> 2, c = idx & 3;
                int rc = (r < mlim) ? r : (mlim - 1);
                raw[j] = *(const uint4*)(g_act + (size_t)(bse + m0 + rc) * I_DIM + k0 + c*8);
            }
            #pragma unroll
            for (int j = 0; j < 4; j++) {
                int idx = j*256 + tid, r = idx >> 3, c = idx & 7;
                rb[j] = *(const float4*)(Db + (size_t)r * I_DIM + k0 + c*4);
            }
        }

        #pragma unroll
        for (int ks = 0; ks < 2; ks++) {
            uint32_t a[2][4];
            #pragma unroll
            for (int i = 0; i < 2; i++) ldsm_x4(a[i], addrA[i] + ks*32);
            uint32_t b[8][2];
            #pragma unroll
            for (int j = 0; j < 8; j++) ldsm_x2(b[j], addrB[j] + ks*32);
            #pragma unroll
            for (int i = 0; i < 2; i++)
                #pragma unroll
                for (int j = 0; j < 8; j++)
                    mma16816(cc[i][j], a[i], b[j]);
        }
        __syncthreads();
    }

    #pragma unroll
    for (int i = 0; i < 2; i++) {
        #pragma unroll
        for (int h = 0; h < 2; h++) {
            int ml = m_base + i*16 + h*8 + (lane >> 2);
            int m  = m0 + ml;
            if (m >= cnt) continue;
            float* prow = g_part + (size_t)(bse + m) * H_DIM + n0;
            #pragma unroll
            for (int j = 0; j < 8; j++) {
                int nl = n_base + j*8 + 2*(lane & 3);
                *(float2*)&prow[nl] = make_float2(cc[i][j][h*2+0], cc[i][j][h*2+1]);
            }
        }
    }
}

// ---------------------------------------------------------------------------
// 5) Combine
// ---------------------------------------------------------------------------
__global__ void combine_kernel(float* __restrict__ out) {
    int t = blockIdx.x;
    int s0 = g_slot_of[2*t], s1 = g_slot_of[2*t + 1];
    const float4* p0 = (const float4*)(g_part + (size_t)s0 * H_DIM);
    const float4* p1 = (const float4*)(g_part + (size_t)s1 * H_DIM);
    float4* o = (float4*)(out + (size_t)t * H_DIM);
    for (int i = threadIdx.x; i < H_DIM / 4; i += blockDim.x) {
        float4 a = p0[i], b = p1[i];
        o[i] = make_float4(a.x + b.x, a.y + b.y, a.z + b.z, a.w + b.w);
    }
}

// ---------------------------------------------------------------------------
extern "C" void kernel_launch(void* const* d_in, const int* in_sizes, int n_in,
                              void* d_out, int out_size) {
    const float* hidden   = (const float*)d_in[0];
    const float* router_w = (const float*)d_in[1];
    const float* gate_w   = (const float*)d_in[2];
    const float* up_w     = (const float*)d_in[3];
    const float* down_w   = (const float*)d_in[4];
    float* out = (float*)d_out;

    router_kernel<<<T_TOK, 512>>>(hidden, router_w);
    build_kernel<<<1, 512>>>();

    // worst-case one expert owns all NPAIR rows -> NPAIR/128 m-tiles
    dim3 gridG(I_DIM / 64, NPAIR / 128, E_NUM);
    gateup_mma<<<gridG, 256>>>(hidden, gate_w, up_w);

    dim3 gridD(H_DIM / 128, NPAIR / 128, E_NUM);
    down_mma<<<gridD, 256>>>(down_w);

    combine_kernel<<<T_TOK, 256>>>(out);
}

// round 4
// speedup vs baseline: 3.9695x; 1.1533x over previous
#include <cuda_runtime.h>
#include <cuda_fp16.h>
#include <math.h>
#include <cstdint>

// Problem constants
#define T_TOK   2048
#define H_DIM   1024
#define E_NUM   16
#define I_DIM   1024
#define NPAIR   (T_TOK*2)

// Scratch (device globals)
__device__ __half g_act [NPAIR * I_DIM];
__device__ float  g_part[NPAIR * H_DIM];
__device__ int    g_expert_of[NPAIR];
__device__ float  g_weight_of[NPAIR];
__device__ int    g_base [E_NUM];
__device__ int    g_count[E_NUM];
__device__ int    g_pair_token[NPAIR];
__device__ float  g_pair_w   [NPAIR];
__device__ int    g_slot_of  [NPAIR];

// ---------------------------------------------------------------------------
// helpers
// ---------------------------------------------------------------------------
__device__ __forceinline__ uint32_t smem_u32(const void* p) {
    uint32_t a;
    asm("{ .reg .u64 t; cvta.to.shared.u64 t, %1; cvt.u32.u64 %0, t; }" : "=r"(a) : "l"(p));
    return a;
}
__device__ __forceinline__ void ldsm_x4(uint32_t* r, uint32_t addr) {
    asm volatile("ldmatrix.sync.aligned.m8n8.x4.shared.b16 {%0,%1,%2,%3}, [%4];"
                 : "=r"(r[0]), "=r"(r[1]), "=r"(r[2]), "=r"(r[3]) : "r"(addr));
}
__device__ __forceinline__ void mma16816(float* c, const uint32_t* a, const uint32_t* b) {
    asm volatile("mma.sync.aligned.m16n8k16.row.col.f32.f16.f16.f32 "
                 "{%0,%1,%2,%3}, {%4,%5,%6,%7}, {%8,%9}, {%0,%1,%2,%3};"
                 : "+f"(c[0]), "+f"(c[1]), "+f"(c[2]), "+f"(c[3])
                 : "r"(a[0]), "r"(a[1]), "r"(a[2]), "r"(a[3]), "r"(b[0]), "r"(b[1]));
}
__device__ __forceinline__ uint32_t packh2(float x, float y) {
    __half2 h = __floats2half2_rn(x, y);
    return *(uint32_t*)&h;
}

// smem row pitch in halfs: 32 (K-slab) + 8 pad => conflict-free ldmatrix
#define PITCH 40

// ---------------------------------------------------------------------------
// 1) Router
// ---------------------------------------------------------------------------
__global__ void router_kernel(const float* __restrict__ x,
                              const float* __restrict__ rw) {
    int t = blockIdx.x;
    int warp = threadIdx.x >> 5, lane = threadIdx.x & 31;
    __shared__ float logits[E_NUM];
    const float* xr = x + (size_t)t * H_DIM;
    const float* wr = rw + (size_t)warp * H_DIM;
    float s = 0.f;
    #pragma unroll 4
    for (int h = lane; h < H_DIM; h += 32) s += xr[h] * wr[h];
    #pragma unroll
    for (int o = 16; o; o >>= 1) s += __shfl_xor_sync(0xffffffffu, s, o);
    if (lane == 0) logits[warp] = s;
    __syncthreads();
    if (threadIdx.x == 0) {
        float sc[E_NUM];
        #pragma unroll
        for (int e = 0; e < E_NUM; e++) sc[e] = 1.f / (1.f + expf(-logits[e]));
        int i0 = 0;
        #pragma unroll
        for (int e = 1; e < E_NUM; e++) if (sc[e] > sc[i0]) i0 = e;
        int i1 = -1;
        #pragma unroll
        for (int e = 0; e < E_NUM; e++) {
            if (e == i0) continue;
            if (i1 < 0 || sc[e] > sc[i1]) i1 = e;
        }
        float w0 = sc[i0], w1 = sc[i1];
        float inv = 1.f / (w0 + w1 + 1e-20f);
        g_expert_of[2*t]   = i0;  g_weight_of[2*t]   = w0 * inv;
        g_expert_of[2*t+1] = i1;  g_weight_of[2*t+1] = w1 * inv;
    }
}

// ---------------------------------------------------------------------------
// 2) Build expert-sorted pair lists
// ---------------------------------------------------------------------------
__global__ void build_kernel() {
    __shared__ unsigned char eid[NPAIR];
    __shared__ int cnt[E_NUM], bs[E_NUM];
    int tid = threadIdx.x;
    for (int p = tid; p < NPAIR; p += blockDim.x)
        eid[p] = (unsigned char)g_expert_of[p];
    __syncthreads();
    if (tid < E_NUM) {
        int c = 0;
        for (int p = 0; p < NPAIR; p++) c += (eid[p] == tid);
        cnt[tid] = c;
    }
    __syncthreads();
    if (tid == 0) {
        int acc = 0;
        for (int e = 0; e < E_NUM; e++) { bs[e] = acc; acc += cnt[e]; }
    }
    __syncthreads();
    int w = tid >> 5, lane = tid & 31;
    if (w < E_NUM) {
        int e = w, pos = bs[e];
        for (int p0 = 0; p0 < NPAIR; p0 += 32) {
            int p = p0 + lane;
            bool m = (eid[p] == e);
            unsigned mask = __ballot_sync(0xffffffffu, m);
            if (m) {
                int s = pos + __popc(mask & ((1u << lane) - 1u));
                g_pair_token[s] = p >> 1;
                g_pair_w[s]     = g_weight_of[p];
                g_slot_of[p]    = s;
            }
            pos += __popc(mask);
        }
    }
    if (tid < E_NUM) { g_base[tid] = bs[tid]; g_count[tid] = cnt[tid]; }
}

// ---------------------------------------------------------------------------
// 3) gateup: double-buffered mma.sync fp16, gate+up fused, SiLU + weight fold
//    CTA tile: 128(M) x 64(N per matrix) x 32(K). 8 warps (4m x 2n), 32x32.
// ---------------------------------------------------------------------------
#define GU_ASTG (128*PITCH*2)   // 10240 B per stage
#define GU_BSTG (64*PITCH*2)    // 5120 B per stage

__global__ __launch_bounds__(256)
void gateup_mma(const float* __restrict__ x,
                const float* __restrict__ gate_w,
                const float* __restrict__ up_w) {
    int e  = blockIdx.z;
    int m0 = blockIdx.y * 128;
    int n0 = blockIdx.x * 64;
    int cnt = g_count[e];
    if (m0 >= cnt) return;
    int bse = g_base[e];

    __shared__ __half As [2][128][PITCH];
    __shared__ __half Bgs[2][64][PITCH];
    __shared__ __half Bus[2][64][PITCH];
    __shared__ int    tok_s[128];
    __shared__ float  wrow_s[128];

    int tid = threadIdx.x, lane = tid & 31, wid = tid >> 5;
    if (tid < 128) {
        int m = m0 + tid;
        bool v = m < cnt;
        int mc = v ? m : (cnt - 1);
        tok_s[tid]  = g_pair_token[bse + mc];
        wrow_s[tid] = v ? g_pair_w[bse + m] : 0.f;
    }
    __syncthreads();

    const float* Gb = gate_w + ((size_t)e << 20) + (size_t)n0 * H_DIM;
    const float* Ub = up_w   + ((size_t)e << 20) + (size_t)n0 * H_DIM;

    int wm = wid & 3, wn = wid >> 2;
    int m_base = wm * 32, n_base = wn * 32;

    uint32_t as_base = smem_u32(&As[0][0][0]);
    uint32_t bg_base = smem_u32(&Bgs[0][0][0]);
    uint32_t bu_base = smem_u32(&Bus[0][0][0]);

    uint32_t addrA[2];
    #pragma unroll
    for (int i = 0; i < 2; i++)
        addrA[i] = as_base + (uint32_t)((m_base + i*16 + (lane & 15)) * (PITCH*2)) + ((lane >> 4) * 16);
    // B pair addresses: x4 covers n16 x k16 (tiles 2jj, 2jj+1)
    uint32_t addrBg[2], addrBu[2];
    #pragma unroll
    for (int jj = 0; jj < 2; jj++) {
        uint32_t row = (uint32_t)(n_base + jj*16 + (lane & 7) + (((lane >> 4) & 1) << 3));
        uint32_t off = row * (PITCH*2) + (((lane >> 3) & 1) * 16);
        addrBg[jj] = bg_base + off;
        addrBu[jj] = bu_base + off;
    }

    float cg[2][4][4] = {}, cu[2][4][4] = {};
    float4 ra[4], rg[2], ru[2];

    // prefetch slab 0
    #pragma unroll
    for (int j = 0; j < 4; j++) {
        int idx = j*256 + tid, r = idx >> 3, c = idx & 7;
        ra[j] = *(const float4*)(x + (size_t)tok_s[r] * H_DIM + c*4);
    }
    #pragma unroll
    for (int j = 0; j < 2; j++) {
        int idx = j*256 + tid, r = idx >> 3, c = idx & 7;
        rg[j] = *(const float4*)(Gb + (size_t)r * H_DIM + c*4);
        ru[j] = *(const float4*)(Ub + (size_t)r * H_DIM + c*4);
    }
    // STS slab 0 into stage 0
    #pragma unroll
    for (int j = 0; j < 4; j++) {
        int idx = j*256 + tid, r = idx >> 3, c = idx & 7;
        uint2 u; u.x = packh2(ra[j].x, ra[j].y); u.y = packh2(ra[j].z, ra[j].w);
        *(uint2*)&As[0][r][c*4] = u;
    }
    #pragma unroll
    for (int j = 0; j < 2; j++) {
        int idx = j*256 + tid, r = idx >> 3, c = idx & 7;
        uint2 ug; ug.x = packh2(rg[j].x, rg[j].y); ug.y = packh2(rg[j].z, rg[j].w);
        *(uint2*)&Bgs[0][r][c*4] = ug;
        uint2 uu; uu.x = packh2(ru[j].x, ru[j].y); uu.y = packh2(ru[j].z, ru[j].w);
        *(uint2*)&Bus[0][r][c*4] = uu;
    }
    __syncthreads();

    const int NIT = H_DIM / 32;
    for (int it = 0; it < NIT; it++) {
        int cur = it & 1;
        // LDG next slab (overlaps with compute below)
        if (it + 1 < NIT) {
            int k0 = (it + 1) * 32;
            #pragma unroll
            for (int j = 0; j < 4; j++) {
                int idx = j*256 + tid, r = idx >> 3, c = idx & 7;
                ra[j] = *(const float4*)(x + (size_t)tok_s[r] * H_DIM + k0 + c*4);
            }
            #pragma unroll
            for (int j = 0; j < 2; j++) {
                int idx = j*256 + tid, r = idx >> 3, c = idx & 7;
                rg[j] = *(const float4*)(Gb + (size_t)r * H_DIM + k0 + c*4);
                ru[j] = *(const float4*)(Ub + (size_t)r * H_DIM + k0 + c*4);
            }
        }
        // compute current stage
        uint32_t stA = as_base ? 0 : 0; (void)stA;
        uint32_t offA = (uint32_t)cur * GU_ASTG;
        uint32_t offB = (uint32_t)cur * GU_BSTG;
        #pragma unroll
        for (int ks = 0; ks < 2; ks++) {
            uint32_t a[2][4];
            #pragma unroll
            for (int i = 0; i < 2; i++) ldsm_x4(a[i], addrA[i] + offA + ks*32);
            uint32_t bg[2][4], bu[2][4];
            #pragma unroll
            for (int jj = 0; jj < 2; jj++) {
                ldsm_x4(bg[jj], addrBg[jj] + offB + ks*32);
                ldsm_x4(bu[jj], addrBu[jj] + offB + ks*32);
            }
            #pragma unroll
            for (int i = 0; i < 2; i++)
                #pragma unroll
                for (int jj = 0; jj < 2; jj++) {
                    mma16816(cg[i][2*jj+0], a[i], &bg[jj][0]);
                    mma16816(cg[i][2*jj+1], a[i], &bg[jj][2]);
                    mma16816(cu[i][2*jj+0], a[i], &bu[jj][0]);
                    mma16816(cu[i][2*jj+1], a[i], &bu[jj][2]);
                }
        }
        // STS next slab into other stage
        if (it + 1 < NIT) {
            int nxt = cur ^ 1;
            #pragma unroll
            for (int j = 0; j < 4; j++) {
                int idx = j*256 + tid, r = idx >> 3, c = idx & 7;
                uint2 u; u.x = packh2(ra[j].x, ra[j].y); u.y = packh2(ra[j].z, ra[j].w);
                *(uint2*)&As[nxt][r][c*4] = u;
            }
            #pragma unroll
            for (int j = 0; j < 2; j++) {
                int idx = j*256 + tid, r = idx >> 3, c = idx & 7;
                uint2 ug; ug.x = packh2(rg[j].x, rg[j].y); ug.y = packh2(rg[j].z, rg[j].w);
                *(uint2*)&Bgs[nxt][r][c*4] = ug;
                uint2 uu; uu.x = packh2(ru[j].x, ru[j].y); uu.y = packh2(ru[j].z, ru[j].w);
                *(uint2*)&Bus[nxt][r][c*4] = uu;
            }
            __syncthreads();
        }
    }

    // epilogue
    #pragma unroll
    for (int i = 0; i < 2; i++) {
        #pragma unroll
        for (int h = 0; h < 2; h++) {
            int ml = m_base + i*16 + h*8 + (lane >> 2);
            int m  = m0 + ml;
            if (m >= cnt) continue;
            float w = wrow_s[ml];
            __half* arow = g_act + (size_t)(bse + m) * I_DIM + n0;
            #pragma unroll
            for (int j = 0; j < 4; j++) {
                int nl = n_base + j*8 + 2*(lane & 3);
                float g0 = cg[i][j][h*2+0], g1 = cg[i][j][h*2+1];
                float u0 = cu[i][j][h*2+0], u1 = cu[i][j][h*2+1];
                float a0 = w * (g0 / (1.f + __expf(-g0))) * u0;
                float a1 = w * (g1 / (1.f + __expf(-g1))) * u1;
                *(uint32_t*)&arow[nl] = packh2(a0, a1);
            }
        }
    }
}

// ---------------------------------------------------------------------------
// 4) down: double-buffered mma.sync fp16 -> g_part (fp32)
//    CTA tile: 64(M) x 128(N) x 32(K). 8 warps (2m x 4n), warp 32x32.
// ---------------------------------------------------------------------------
#define DN_ASTG (64*PITCH*2)    // 5120 B per stage
#define DN_BSTG (128*PITCH*2)   // 10240 B per stage

__global__ __launch_bounds__(256)
void down_mma(const float* __restrict__ down_w) {
    int e  = blockIdx.z;
    int m0 = blockIdx.y * 64;
    int n0 = blockIdx.x * 128;
    int cnt = g_count[e];
    if (m0 >= cnt) return;
    int bse = g_base[e];

    __shared__ __half As[2][64][PITCH];
    __shared__ __half Bs[2][128][PITCH];

    int tid = threadIdx.x, lane = tid & 31, wid = tid >> 5;
    int mlim = cnt - m0;

    const float* Db = down_w + ((size_t)e << 20) + (size_t)n0 * I_DIM;

    int wm = wid & 1, wn = wid >> 1;
    int m_base = wm * 32, n_base = wn * 32;

    uint32_t as_base = smem_u32(&As[0][0][0]);
    uint32_t bs_base = smem_u32(&Bs[0][0][0]);
    uint32_t addrA[2];
    #pragma unroll
    for (int i = 0; i < 2; i++)
        addrA[i] = as_base + (uint32_t)((m_base + i*16 + (lane & 15)) * (PITCH*2)) + ((lane >> 4) * 16);
    uint32_t addrB[2];
    #pragma unroll
    for (int jj = 0; jj < 2; jj++) {
        uint32_t row = (uint32_t)(n_base + jj*16 + (lane & 7) + (((lane >> 4) & 1) << 3));
        addrB[jj] = bs_base + row * (PITCH*2) + (((lane >> 3) & 1) * 16);
    }

    float cc[2][4][4] = {};

    // A: 1 uint4 (8 halfs) per thread; B: 4 float4 per thread
    int arr = tid >> 2, arc = tid & 3;
    int arc_r = (arr < mlim) ? arr : (mlim - 1);
    const __half* Arow = g_act + (size_t)(bse + m0 + arc_r) * I_DIM;

    uint4  ra;
    float4 rb[4];
    ra = *(const uint4*)(Arow + arc*8);
    #pragma unroll
    for (int j = 0; j < 4; j++) {
        int idx = j*256 + tid, r = idx >> 3, c = idx & 7;
        rb[j] = *(const float4*)(Db + (size_t)r * I_DIM + c*4);
    }
    *(uint4*)&As[0][arr][arc*8] = ra;
    #pragma unroll
    for (int j = 0; j < 4; j++) {
        int idx = j*256 + tid, r = idx >> 3, c = idx & 7;
        uint2 u; u.x = packh2(rb[j].x, rb[j].y); u.y = packh2(rb[j].z, rb[j].w);
        *(uint2*)&Bs[0][r][c*4] = u;
    }
    __syncthreads();

    const int NIT = I_DIM / 32;
    for (int it = 0; it < NIT; it++) {
        int cur = it & 1;
        if (it + 1 < NIT) {
            int k0 = (it + 1) * 32;
            ra = *(const uint4*)(Arow + k0 + arc*8);
            #pragma unroll
            for (int j = 0; j < 4; j++) {
                int idx = j*256 + tid, r = idx >> 3, c = idx & 7;
                rb[j] = *(const float4*)(Db + (size_t)r * I_DIM + k0 + c*4);
            }
        }
        uint32_t offA = (uint32_t)cur * DN_ASTG;
        uint32_t offB = (uint32_t)cur * DN_BSTG;
        #pragma unroll
        for (int ks = 0; ks < 2; ks++) {
            uint32_t a[2][4];
            #pragma unroll
            for (int i = 0; i < 2; i++) ldsm_x4(a[i], addrA[i] + offA + ks*32);
            uint32_t b[2][4];
            #pragma unroll
            for (int jj = 0; jj < 2; jj++) ldsm_x4(b[jj], addrB[jj] + offB + ks*32);
            #pragma unroll
            for (int i = 0; i < 2; i++)
                #pragma unroll
                for (int jj = 0; jj < 2; jj++) {
                    mma16816(cc[i][2*jj+0], a[i], &b[jj][0]);
                    mma16816(cc[i][2*jj+1], a[i], &b[jj][2]);
                }
        }
        if (it + 1 < NIT) {
            int nxt = cur ^ 1;
            *(uint4*)&As[nxt][arr][arc*8] = ra;
            #pragma unroll
            for (int j = 0; j < 4; j++) {
                int idx = j*256 + tid, r = idx >> 3, c = idx & 7;
                uint2 u; u.x = packh2(rb[j].x, rb[j].y); u.y = packh2(rb[j].z, rb[j].w);
                *(uint2*)&Bs[nxt][r][c*4] = u;
            }
            __syncthreads();
        }
    }

    #pragma unroll
    for (int i = 0; i < 2; i++) {
        #pragma unroll
        for (int h = 0; h < 2; h++) {
            int ml = m_base + i*16 + h*8 + (lane >> 2);
            int m  = m0 + ml;
            if (m >= cnt) continue;
            float* prow = g_part + (size_t)(bse + m) * H_DIM + n0;
            #pragma unroll
            for (int j = 0; j < 4; j++) {
                int nl = n_base + j*8 + 2*(lane & 3);
                *(float2*)&prow[nl] = make_float2(cc[i][j][h*2+0], cc[i][j][h*2+1]);
            }
        }
    }
}

// ---------------------------------------------------------------------------
// 5) Combine
// ---------------------------------------------------------------------------
__global__ void combine_kernel(float* __restrict__ out) {
    int t = blockIdx.x;
    int s0 = g_slot_of[2*t], s1 = g_slot_of[2*t + 1];
    const float4* p0 = (const float4*)(g_part + (size_t)s0 * H_DIM);
    const float4* p1 = (const float4*)(g_part + (size_t)s1 * H_DIM);
    float4* o = (float4*)(out + (size_t)t * H_DIM);
    for (int i = threadIdx.x; i < H_DIM / 4; i += blockDim.x) {
        float4 a = p0[i], b = p1[i];
        o[i] = make_float4(a.x + b.x, a.y + b.y, a.z + b.z, a.w + b.w);
    }
}

// ---------------------------------------------------------------------------
extern "C" void kernel_launch(void* const* d_in, const int* in_sizes, int n_in,
                              void* d_out, int out_size) {
    const float* hidden   = (const float*)d_in[0];
    const float* router_w = (const float*)d_in[1];
    const float* gate_w   = (const float*)d_in[2];
    const float* up_w     = (const float*)d_in[3];
    const float* down_w   = (const float*)d_in[4];
    float* out = (float*)d_out;

    router_kernel<<<T_TOK, 512>>>(hidden, router_w);
    build_kernel<<<1, 512>>>();

    dim3 gridG(I_DIM / 64, NPAIR / 128, E_NUM);
    gateup_mma<<<gridG, 256>>>(hidden, gate_w, up_w);

    dim3 gridD(H_DIM / 128, NPAIR / 64, E_NUM);
    down_mma<<<gridD, 256>>>(down_w);

    combine_kernel<<<T_TOK, 256>>>(out);
}